// round 13
// baseline (speedup 1.0000x reference)
#include <cuda_runtime.h>

// Modelev12: 2-layer LSTM, H=48, B=4096, T=512, F=64
// R12: 4 warps x 8 batches (1 warp/SMSP). Weight L1 traffic halved vs R9.
// In-warp software pipeline: act0 interleaved with layer1 matvec over h1_old,
// hiding MUFU under the FFMA2 stream. Warp-independent islands (no cross-warp
// sync in the loop). f32x2 packed over batch pairs.
#define H      48
#define TOBS   512
#define FPRED  64
#define TTOT   (TOBS + FPRED)     // 576
#define BATCH  4096
#define MBC    32                 // batches per CTA (4 warps x 8)
#define NCTA   128
#define NTHR   128                // 4 warps

typedef unsigned long long ull;

// float-offset shared layout
#define OFF_WT0 0                        // [48][192]  Whh0^T scalar
#define OFF_WT1 9216                     // [96][192]  [Wih1|Whh1]^T scalar
#define OFF_WI0 27648                    // [192]
#define OFF_B0  27840                    // [192]
#define OFF_B1  28032                    // [192]
#define OFF_HC  28224                    // 4 warps x [96][8]  h state
#define OFF_XC  (OFF_HC + 4*768)         // 4 warps x 16 floats (ull[4] used)
#define OFF_GT  (OFF_XC + 4*16)          // 4 warps x [192]x10  gates
#define GSTR    10
#define SMEM_FLOATS (OFF_GT + 4*192*GSTR)
#define SMEM_BYTES  (SMEM_FLOATS * 4)    // ~156 KB

__device__ __forceinline__ ull ffma2(ull a, ull b, ull c) {
    ull d;
    asm("fma.rn.f32x2 %0, %1, %2, %3;" : "=l"(d) : "l"(a), "l"(b), "l"(c));
    return d;
}
__device__ __forceinline__ ull pack1(float v) {            // {v, v}
    ull d; asm("mov.b64 %0, {%1, %1};" : "=l"(d) : "f"(v)); return d;
}
__device__ __forceinline__ ull pack2(float lo, float hi) {
    ull d; asm("mov.b64 %0, {%1, %2};" : "=l"(d) : "f"(lo), "f"(hi)); return d;
}
__device__ __forceinline__ float fsig(float xv) {
    float e = __expf(-xv);
    return __fdividef(1.0f, 1.0f + e);
}
__device__ __forceinline__ float ftanh(float xv) {
    float a = fabsf(xv);
    float e = __expf(-2.0f * a);
    float r = __fdividef(1.0f - e, 1.0f + e);
    return copysignf(r, xv);
}

__global__ void __launch_bounds__(NTHR, 1) lstm576_b8_kernel(
    const float* __restrict__ x,
    const float* __restrict__ wih0, const float* __restrict__ whh0,
    const float* __restrict__ bih0, const float* __restrict__ bhh0,
    const float* __restrict__ wih1, const float* __restrict__ whh1,
    const float* __restrict__ bih1, const float* __restrict__ bhh1,
    const float* __restrict__ wlin, const float* __restrict__ blin,
    float* __restrict__ out)
{
    extern __shared__ float sm[];
    float* WT0 = sm + OFF_WT0;
    float* WT1 = sm + OFF_WT1;
    float* WI0 = sm + OFF_WI0;
    float* B0s = sm + OFF_B0;
    float* B1s = sm + OFF_B1;

    const int tid  = threadIdx.x;
    const int lane = tid & 31;
    const int w    = tid >> 5;        // warp 0..3 (one per SMSP)
    const int bp   = lane & 3;        // act/head batch pair
    const int jb   = lane >> 2;       // act/head j base (0..7)
    const int gbw  = blockIdx.x * MBC + 8 * w;   // warp's batch base

    float* HCw = sm + OFF_HC + w * 768;          // [96][8]
    ull*   XCu = (ull*)(sm + OFF_XC) + w * 8;    // [4] packed x pairs
    float* GTw = sm + OFF_GT + w * 192 * GSTR;   // [192][10]

    // ---- one-time staging ----
    for (int i = tid; i < 48 * 192; i += NTHR) {
        int k = i / 192, r = i - k * 192;
        WT0[i] = whh0[r * 48 + k];
    }
    for (int i = tid; i < 96 * 192; i += NTHR) {
        int k = i / 192, r = i - k * 192;
        WT1[i] = (k < 48) ? wih1[r * 48 + k] : whh1[r * 48 + (k - 48)];
    }
    for (int i = tid; i < 192; i += NTHR) {
        WI0[i] = wih0[i];
        B0s[i] = bih0[i] + bhh0[i];
        B1s[i] = bih1[i] + bhh1[i];
    }
    for (int i = tid; i < 4 * 768; i += NTHR) sm[OFF_HC + i] = 0.0f;
    if (lane < 4)
        XCu[lane] = pack2(x[(size_t)(gbw + 2 * lane) * TOBS],
                          x[(size_t)(gbw + 2 * lane + 1) * TOBS]);
    const float blv = blin[0];

    float wlj[6];
#pragma unroll
    for (int i = 0; i < 6; i++) wlj[i] = wlin[jb + 8 * i];

    float c0[12], c1[12];
#pragma unroll
    for (int i = 0; i < 12; i++) { c0[i] = 0.0f; c1[i] = 0.0f; }

    __syncthreads();   // staging done (only block-wide sync)

    ull acc[6][4];

    for (int t = 0; t < TTOT; t++) {
        // prefetch next teacher-forced inputs (lanes 0..3)
        float xp0 = 0.0f, xp1 = 0.0f;
        if (lane < 4 && (t + 1) < TOBS) {
            xp0 = x[(size_t)(gbw + 2 * lane) * TOBS + (t + 1)];
            xp1 = x[(size_t)(gbw + 2 * lane + 1) * TOBS + (t + 1)];
        }

        // ======== P1: layer0 matvec (x + h0_old) -> gates0 ========
        {
            ulonglong2 xq0 = ((const ulonglong2*)XCu)[0];
            ulonglong2 xq1 = ((const ulonglong2*)XCu)[1];
            ull xx[4] = { xq0.x, xq0.y, xq1.x, xq1.y };
#pragma unroll
            for (int m = 0; m < 6; m++) {
                ull wip = pack1(WI0[lane + 32 * m]);
                ull b0p = pack1(B0s[lane + 32 * m]);
#pragma unroll
                for (int b = 0; b < 4; b++) acc[m][b] = ffma2(wip, xx[b], b0p);
            }
#pragma unroll 4
            for (int kt = 0; kt < 48; kt += 2) {
                const ulonglong2* hp = (const ulonglong2*)(HCw + kt * 8);
                ulonglong2 hA = hp[0], hB = hp[1], hC = hp[2], hD = hp[3];
                float w0[6], w1[6];
#pragma unroll
                for (int m = 0; m < 6; m++) {
                    w0[m] = WT0[kt * 192 + lane + 32 * m];
                    w1[m] = WT0[(kt + 1) * 192 + lane + 32 * m];
                }
#pragma unroll
                for (int m = 0; m < 6; m++) {
                    ull wp = pack1(w0[m]);
                    acc[m][0] = ffma2(wp, hA.x, acc[m][0]);
                    acc[m][1] = ffma2(wp, hA.y, acc[m][1]);
                    acc[m][2] = ffma2(wp, hB.x, acc[m][2]);
                    acc[m][3] = ffma2(wp, hB.y, acc[m][3]);
                }
#pragma unroll
                for (int m = 0; m < 6; m++) {
                    ull wp = pack1(w1[m]);
                    acc[m][0] = ffma2(wp, hC.x, acc[m][0]);
                    acc[m][1] = ffma2(wp, hC.y, acc[m][1]);
                    acc[m][2] = ffma2(wp, hD.x, acc[m][2]);
                    acc[m][3] = ffma2(wp, hD.y, acc[m][3]);
                }
            }
#pragma unroll
            for (int m = 0; m < 6; m++)
#pragma unroll
                for (int b = 0; b < 4; b++)
                    *(ull*)(GTw + (lane + 32 * m) * GSTR + 2 * b) = acc[m][b];
        }
        __syncwarp();

        // ======== P2: act0 (MUFU) interleaved with layer1 matvec over h1_old ========
        {
            // act0: h0_new elements (bp, j=jb+8i); writes HC rows 0..47
#pragma unroll
            for (int i = 0; i < 6; i++) {
                int j = jb + 8 * i;
                float2 gi = *(const float2*)(GTw + (j)       * GSTR + 2 * bp);
                float2 gf = *(const float2*)(GTw + (48 + j)  * GSTR + 2 * bp);
                float2 gg = *(const float2*)(GTw + (96 + j)  * GSTR + 2 * bp);
                float2 go = *(const float2*)(GTw + (144 + j) * GSTR + 2 * bp);
                float clo = fmaf(fsig(gf.x), c0[2 * i],     fsig(gi.x) * ftanh(gg.x));
                float chi = fmaf(fsig(gf.y), c0[2 * i + 1], fsig(gi.y) * ftanh(gg.y));
                c0[2 * i] = clo; c0[2 * i + 1] = chi;
                *(ull*)(HCw + j * 8 + 2 * bp) =
                    pack2(fsig(go.x) * ftanh(clo), fsig(go.y) * ftanh(chi));
            }
            // matvec1a: k = 48..95 (h1_old region, independent of act0)
#pragma unroll
            for (int m = 0; m < 6; m++) {
                ull b1p = pack1(B1s[lane + 32 * m]);
#pragma unroll
                for (int b = 0; b < 4; b++) acc[m][b] = b1p;
            }
#pragma unroll 4
            for (int kt = 48; kt < 96; kt += 2) {
                const ulonglong2* hp = (const ulonglong2*)(HCw + kt * 8);
                ulonglong2 hA = hp[0], hB = hp[1], hC = hp[2], hD = hp[3];
                float w0[6], w1[6];
#pragma unroll
                for (int m = 0; m < 6; m++) {
                    w0[m] = WT1[kt * 192 + lane + 32 * m];
                    w1[m] = WT1[(kt + 1) * 192 + lane + 32 * m];
                }
#pragma unroll
                for (int m = 0; m < 6; m++) {
                    ull wp = pack1(w0[m]);
                    acc[m][0] = ffma2(wp, hA.x, acc[m][0]);
                    acc[m][1] = ffma2(wp, hA.y, acc[m][1]);
                    acc[m][2] = ffma2(wp, hB.x, acc[m][2]);
                    acc[m][3] = ffma2(wp, hB.y, acc[m][3]);
                }
#pragma unroll
                for (int m = 0; m < 6; m++) {
                    ull wp = pack1(w1[m]);
                    acc[m][0] = ffma2(wp, hC.x, acc[m][0]);
                    acc[m][1] = ffma2(wp, hC.y, acc[m][1]);
                    acc[m][2] = ffma2(wp, hD.x, acc[m][2]);
                    acc[m][3] = ffma2(wp, hD.y, acc[m][3]);
                }
            }
        }
        __syncwarp();   // h0_new visible to all lanes

        // ======== P3: layer1 matvec over h0_new (k = 0..47) -> gates1 ========
        {
#pragma unroll 4
            for (int kt = 0; kt < 48; kt += 2) {
                const ulonglong2* hp = (const ulonglong2*)(HCw + kt * 8);
                ulonglong2 hA = hp[0], hB = hp[1], hC = hp[2], hD = hp[3];
                float w0[6], w1[6];
#pragma unroll
                for (int m = 0; m < 6; m++) {
                    w0[m] = WT1[kt * 192 + lane + 32 * m];
                    w1[m] = WT1[(kt + 1) * 192 + lane + 32 * m];
                }
#pragma unroll
                for (int m = 0; m < 6; m++) {
                    ull wp = pack1(w0[m]);
                    acc[m][0] = ffma2(wp, hA.x, acc[m][0]);
                    acc[m][1] = ffma2(wp, hA.y, acc[m][1]);
                    acc[m][2] = ffma2(wp, hB.x, acc[m][2]);
                    acc[m][3] = ffma2(wp, hB.y, acc[m][3]);
                }
#pragma unroll
                for (int m = 0; m < 6; m++) {
                    ull wp = pack1(w1[m]);
                    acc[m][0] = ffma2(wp, hC.x, acc[m][0]);
                    acc[m][1] = ffma2(wp, hC.y, acc[m][1]);
                    acc[m][2] = ffma2(wp, hD.x, acc[m][2]);
                    acc[m][3] = ffma2(wp, hD.y, acc[m][3]);
                }
            }
#pragma unroll
            for (int m = 0; m < 6; m++)
#pragma unroll
                for (int b = 0; b < 4; b++)
                    *(ull*)(GTw + (lane + 32 * m) * GSTR + 2 * b) = acc[m][b];
        }
        __syncwarp();

        // ======== P4: act1 + fused head ========
        {
            float s_lo = 0.0f, s_hi = 0.0f;
#pragma unroll
            for (int i = 0; i < 6; i++) {
                int j = jb + 8 * i;
                float2 gi = *(const float2*)(GTw + (j)       * GSTR + 2 * bp);
                float2 gf = *(const float2*)(GTw + (48 + j)  * GSTR + 2 * bp);
                float2 gg = *(const float2*)(GTw + (96 + j)  * GSTR + 2 * bp);
                float2 go = *(const float2*)(GTw + (144 + j) * GSTR + 2 * bp);
                float clo = fmaf(fsig(gf.x), c1[2 * i],     fsig(gi.x) * ftanh(gg.x));
                float chi = fmaf(fsig(gf.y), c1[2 * i + 1], fsig(gi.y) * ftanh(gg.y));
                c1[2 * i] = clo; c1[2 * i + 1] = chi;
                float hlo = fsig(go.x) * ftanh(clo);
                float hhi = fsig(go.y) * ftanh(chi);
                *(ull*)(HCw + (48 + j) * 8 + 2 * bp) = pack2(hlo, hhi);
                s_lo = fmaf(hlo, wlj[i], s_lo);
                s_hi = fmaf(hhi, wlj[i], s_hi);
            }
            // reduce over the 8 lanes sharing this bp (xor 4, 8, 16)
            s_lo += __shfl_xor_sync(0xFFFFFFFFu, s_lo, 4);
            s_hi += __shfl_xor_sync(0xFFFFFFFFu, s_hi, 4);
            s_lo += __shfl_xor_sync(0xFFFFFFFFu, s_lo, 8);
            s_hi += __shfl_xor_sync(0xFFFFFFFFu, s_hi, 8);
            s_lo += __shfl_xor_sync(0xFFFFFFFFu, s_lo, 16);
            s_hi += __shfl_xor_sync(0xFFFFFFFFu, s_hi, 16);
            if (lane < 4) {
                s_lo += blv; s_hi += blv;
                out[(size_t)(gbw + 2 * lane)     * TTOT + t] = s_lo;
                out[(size_t)(gbw + 2 * lane + 1) * TTOT + t] = s_hi;
                float nx0 = ((t + 1) < TOBS) ? xp0 : s_lo;
                float nx1 = ((t + 1) < TOBS) ? xp1 : s_hi;
                XCu[lane] = pack2(nx0, nx1);
            }
        }
        __syncwarp();
    }
}

extern "C" void kernel_launch(void* const* d_in, const int* in_sizes, int n_in,
                              void* d_out, int out_size)
{
    (void)in_sizes; (void)n_in; (void)out_size;
    const float* x    = (const float*)d_in[0];
    const float* wih0 = (const float*)d_in[1];
    const float* whh0 = (const float*)d_in[2];
    const float* bih0 = (const float*)d_in[3];
    const float* bhh0 = (const float*)d_in[4];
    const float* wih1 = (const float*)d_in[5];
    const float* whh1 = (const float*)d_in[6];
    const float* bih1 = (const float*)d_in[7];
    const float* bhh1 = (const float*)d_in[8];
    const float* wlin = (const float*)d_in[9];
    const float* blin = (const float*)d_in[10];
    float* out = (float*)d_out;

    cudaFuncSetAttribute(lstm576_b8_kernel,
                         cudaFuncAttributeMaxDynamicSharedMemorySize, SMEM_BYTES);
    lstm576_b8_kernel<<<NCTA, NTHR, SMEM_BYTES>>>(
        x, wih0, whh0, bih0, bhh0, wih1, whh1, bih1, bhh1, wlin, blin, out);
}

// round 15
// speedup vs baseline: 1.5569x; 1.5569x over previous
#include <cuda_runtime.h>
#include <cuda_bf16.h>
#include <cstdint>

// Modelev12: 2-layer LSTM, H=48, B=4096, T=512, F=64
// R14: cooperative tensor-core path via portable mma.sync (HMMA) + ldmatrix.
//   Per CTA (grid 128): batch 32. gates[192,32] = Wcat @ Xcat, bf16 2-term
//   split (Whi*Xhi + Whi*Xlo + Wlo*Xhi), fp32 accum in registers.
//   8 warps = 4 M-groups (3x16-row tiles) x 2 N-halves (16 cols).
//   Activations: identical fp32 exp-based math as the scalar kernels.
#define TOBS   512
#define FPRED  64
#define TTOT   576
#define BATCH  4096
#define MBC    32
#define NCTA   128
#define NTHR   256

// ---- SMEM byte layout ----
// A0: bf16 [192][136]  (cols 0-63 Whi, 64-127 Wlo, 128-135 pad) stride 272B
// A1: bf16 [192][200]  (cols 0-95 Whi, 96-191 Wlo, 192-199 pad) stride 400B
// X0: bf16 [128][40]   (rows 0-63 hi: 0=x,1-48=h0; rows 64-127 lo) stride 80B
// X1: bf16 [192][40]   (rows 0-95 hi: h0|h1; rows 96-191 lo)
#define SB_A0   0
#define SB_A1   52224                    // 192*136*2
#define SB_X0   129024                   // +192*200*2
#define SB_X1   139264                   // +128*40*2
#define SB_GT   154624                   // +192*40*2 ; f32 [192][34]
#define SB_HP   180736                   // +192*34*4 ; f32 [48][33]
#define SB_BI0  187072                   // +48*33*4
#define SB_BI1  187840
#define SB_WL   188608
#define SMEM_BYTES 188800

#define ASTR0   272
#define ASTR1   400
#define XSTR    80

__device__ __forceinline__ uint32_t smem_u32(const void* p) {
    uint32_t a;
    asm("{ .reg .u64 t; cvta.to.shared.u64 t, %1; cvt.u32.u64 %0, t; }" : "=r"(a) : "l"(p));
    return a;
}
__device__ __forceinline__ void ldsm4(uint32_t r[4], uint32_t addr) {
    asm volatile("ldmatrix.sync.aligned.m8n8.x4.shared.b16 {%0,%1,%2,%3}, [%4];"
                 : "=r"(r[0]), "=r"(r[1]), "=r"(r[2]), "=r"(r[3]) : "r"(addr));
}
__device__ __forceinline__ void ldsm4t(uint32_t r[4], uint32_t addr) {
    asm volatile("ldmatrix.sync.aligned.m8n8.x4.trans.shared.b16 {%0,%1,%2,%3}, [%4];"
                 : "=r"(r[0]), "=r"(r[1]), "=r"(r[2]), "=r"(r[3]) : "r"(addr));
}
__device__ __forceinline__ void mma16816(float d[4], const uint32_t a[4], const uint32_t b[2]) {
    asm volatile("mma.sync.aligned.m16n8k16.row.col.f32.bf16.bf16.f32 "
                 "{%0,%1,%2,%3}, {%4,%5,%6,%7}, {%8,%9}, {%0,%1,%2,%3};"
                 : "+f"(d[0]), "+f"(d[1]), "+f"(d[2]), "+f"(d[3])
                 : "r"(a[0]), "r"(a[1]), "r"(a[2]), "r"(a[3]), "r"(b[0]), "r"(b[1]));
}
__device__ __forceinline__ float fsig(float xv) {
    float e = __expf(-xv);
    return __fdividef(1.0f, 1.0f + e);
}
__device__ __forceinline__ float ftanh(float xv) {
    float a = fabsf(xv);
    float e = __expf(-2.0f * a);
    float r = __fdividef(1.0f - e, 1.0f + e);
    return copysignf(r, xv);
}
__device__ __forceinline__ unsigned short bfhi(float v) {
    __nv_bfloat16 h = __float2bfloat16(v);
    return *(unsigned short*)&h;
}
__device__ __forceinline__ unsigned short bflo(float v) {
    __nv_bfloat16 h = __float2bfloat16(v);
    __nv_bfloat16 l = __float2bfloat16(v - __bfloat162float(h));
    return *(unsigned short*)&l;
}
__device__ __forceinline__ float w0cat(const float* wih0, const float* whh0, int r, int k) {
    if (k == 0) return wih0[r];
    if (k < 49) return whh0[r * 48 + (k - 1)];
    return 0.0f;
}
__device__ __forceinline__ float w1cat(const float* wih1, const float* whh1, int r, int k) {
    if (k < 48)  return wih1[r * 48 + k];
    if (k < 96)  return whh1[r * 48 + (k - 48)];
    return 0.0f;
}

__global__ void __launch_bounds__(NTHR, 1) lstm576_hmma_kernel(
    const float* __restrict__ x,
    const float* __restrict__ wih0, const float* __restrict__ whh0,
    const float* __restrict__ bih0, const float* __restrict__ bhh0,
    const float* __restrict__ wih1, const float* __restrict__ whh1,
    const float* __restrict__ bih1, const float* __restrict__ bhh1,
    const float* __restrict__ wlin, const float* __restrict__ blin,
    float* __restrict__ out)
{
    extern __shared__ char smem[];
    const uint32_t sb = smem_u32(smem);
    const int tid  = threadIdx.x, lane = tid & 31, wid = tid >> 5;
    const int gb0  = blockIdx.x * MBC;

    unsigned short* A0u = (unsigned short*)(smem + SB_A0);
    unsigned short* A1u = (unsigned short*)(smem + SB_A1);
    unsigned short* X0u = (unsigned short*)(smem + SB_X0);
    unsigned short* X1u = (unsigned short*)(smem + SB_X1);
    float* GT  = (float*)(smem + SB_GT);
    float* HP  = (float*)(smem + SB_HP);
    float* BI0 = (float*)(smem + SB_BI0);
    float* BI1 = (float*)(smem + SB_BI1);
    float* WLs = (float*)(smem + SB_WL);

    // ---- one-time staging ----
    for (int i = tid; i < 192 * 136; i += NTHR) {
        int r = i / 136, c = i - r * 136;
        unsigned short v = 0;
        if (c < 64)       v = bfhi(w0cat(wih0, whh0, r, c));
        else if (c < 128) v = bflo(w0cat(wih0, whh0, r, c - 64));
        A0u[i] = v;
    }
    for (int i = tid; i < 192 * 200; i += NTHR) {
        int r = i / 200, c = i - r * 200;
        unsigned short v = 0;
        if (c < 96)       v = bfhi(w1cat(wih1, whh1, r, c));
        else if (c < 192) v = bflo(w1cat(wih1, whh1, r, c - 96));
        A1u[i] = v;
    }
    for (int i = tid; i < 128 * 40; i += NTHR) X0u[i] = 0;
    for (int i = tid; i < 192 * 40; i += NTHR) X1u[i] = 0;
    for (int i = tid; i < 192; i += NTHR) {
        BI0[i] = bih0[i] + bhh0[i];
        BI1[i] = bih1[i] + bhh1[i];
    }
    if (tid < 48) WLs[tid] = wlin[tid];
    __syncthreads();
    if (tid < 32) {
        float v = x[(size_t)(gb0 + tid) * TOBS];
        X0u[tid]            = bfhi(v);   // row 0 (x hi)
        X0u[64 * 40 + tid]  = bflo(v);   // row 64 (x lo)
    }
    const float blv = blin[0];

    // warp tiling: mw in 0..3 -> m-tiles {mw, mw+4, mw+8}; nh -> cols 16*nh..+15
    const int mw = wid & 3, nh = wid >> 2, n0 = nh * 16;
    const int trow = lane & 7, tg = lane >> 3;
    const int off1 = (tg & 1) * 8;     // m-offset (A) / k-offset (B)
    const int off2 = (tg >> 1) * 8;    // k-offset (A) / n-offset (B)
    const int gid  = lane >> 2, ctid = lane & 3;

    float c0[6], c1[6];
#pragma unroll
    for (int i = 0; i < 6; i++) { c0[i] = 0.0f; c1[i] = 0.0f; }

    __syncthreads();

    for (int t = 0; t < TTOT; t++) {
        float xn = 0.0f;
        if (wid == 6 && (t + 1) < TOBS)
            xn = x[(size_t)(gb0 + lane) * TOBS + (t + 1)];

        // ======== GEMM0: gates0 = W0cat @ X0cat ========
        {
            float d[3][2][4];
#pragma unroll
            for (int a = 0; a < 3; a++)
#pragma unroll
                for (int b = 0; b < 2; b++)
#pragma unroll
                    for (int q = 0; q < 4; q++) d[a][b][q] = 0.0f;
#pragma unroll
            for (int ks = 0; ks < 4; ks++) {
                int kb = ks * 16;
                uint32_t bh[4], bl[4];
                uint32_t baddr = sb + SB_X0 + (uint32_t)((kb + off1 + trow) * XSTR + (n0 + off2) * 2);
                ldsm4t(bh, baddr);
                ldsm4t(bl, baddr + 64 * XSTR);   // Xlo rows +64
#pragma unroll
                for (int mt = 0; mt < 3; mt++) {
                    int m0 = (mw + mt * 4) * 16;
                    uint32_t aaddr = sb + SB_A0 + (uint32_t)((m0 + off1 + trow) * ASTR0 + (kb + off2) * 2);
                    uint32_t ah[4], al[4];
                    ldsm4(ah, aaddr);
                    ldsm4(al, aaddr + 128);      // Wlo cols +64 (*2B)
                    mma16816(d[mt][0], ah, &bh[0]);
                    mma16816(d[mt][0], ah, &bl[0]);
                    mma16816(d[mt][0], al, &bh[0]);
                    mma16816(d[mt][1], ah, &bh[2]);
                    mma16816(d[mt][1], ah, &bl[2]);
                    mma16816(d[mt][1], al, &bh[2]);
                }
            }
#pragma unroll
            for (int mt = 0; mt < 3; mt++) {
                int m0 = (mw + mt * 4) * 16;
#pragma unroll
                for (int nt = 0; nt < 2; nt++) {
                    int cb = n0 + nt * 8 + 2 * ctid;
                    *(float2*)(GT + (m0 + gid) * 34 + cb)     = make_float2(d[mt][nt][0], d[mt][nt][1]);
                    *(float2*)(GT + (m0 + gid + 8) * 34 + cb) = make_float2(d[mt][nt][2], d[mt][nt][3]);
                }
            }
        }
        __syncthreads();

        // ======== act0 -> h0 splits into X1 (rows j / 96+j) and X0 (rows 1+j / 65+j) ========
#pragma unroll
        for (int i = 0; i < 6; i++) {
            int e = tid + NTHR * i, b = e & 31, j = e >> 5;
            float gi = GT[j * 34 + b]          + BI0[j];
            float gf = GT[(48 + j) * 34 + b]   + BI0[48 + j];
            float gg = GT[(96 + j) * 34 + b]   + BI0[96 + j];
            float go = GT[(144 + j) * 34 + b]  + BI0[144 + j];
            float c = fmaf(fsig(gf), c0[i], fsig(gi) * ftanh(gg));
            c0[i] = c;
            float h = fsig(go) * ftanh(c);
            unsigned short hh = bfhi(h), hl = bflo(h);
            X1u[j * 40 + b]          = hh;
            X1u[(96 + j) * 40 + b]   = hl;
            X0u[(1 + j) * 40 + b]    = hh;
            X0u[(65 + j) * 40 + b]   = hl;
        }
        __syncthreads();

        // ======== GEMM1: gates1 = W1cat @ X1cat ========
        {
            float d[3][2][4];
#pragma unroll
            for (int a = 0; a < 3; a++)
#pragma unroll
                for (int b = 0; b < 2; b++)
#pragma unroll
                    for (int q = 0; q < 4; q++) d[a][b][q] = 0.0f;
#pragma unroll
            for (int ks = 0; ks < 6; ks++) {
                int kb = ks * 16;
                uint32_t bh[4], bl[4];
                uint32_t baddr = sb + SB_X1 + (uint32_t)((kb + off1 + trow) * XSTR + (n0 + off2) * 2);
                ldsm4t(bh, baddr);
                ldsm4t(bl, baddr + 96 * XSTR);   // Xlo rows +96
#pragma unroll
                for (int mt = 0; mt < 3; mt++) {
                    int m0 = (mw + mt * 4) * 16;
                    uint32_t aaddr = sb + SB_A1 + (uint32_t)((m0 + off1 + trow) * ASTR1 + (kb + off2) * 2);
                    uint32_t ah[4], al[4];
                    ldsm4(ah, aaddr);
                    ldsm4(al, aaddr + 192);      // Wlo cols +96 (*2B)
                    mma16816(d[mt][0], ah, &bh[0]);
                    mma16816(d[mt][0], ah, &bl[0]);
                    mma16816(d[mt][0], al, &bh[0]);
                    mma16816(d[mt][1], ah, &bh[2]);
                    mma16816(d[mt][1], ah, &bl[2]);
                    mma16816(d[mt][1], al, &bh[2]);
                }
            }
#pragma unroll
            for (int mt = 0; mt < 3; mt++) {
                int m0 = (mw + mt * 4) * 16;
#pragma unroll
                for (int nt = 0; nt < 2; nt++) {
                    int cb = n0 + nt * 8 + 2 * ctid;
                    *(float2*)(GT + (m0 + gid) * 34 + cb)     = make_float2(d[mt][nt][0], d[mt][nt][1]);
                    *(float2*)(GT + (m0 + gid + 8) * 34 + cb) = make_float2(d[mt][nt][2], d[mt][nt][3]);
                }
            }
        }
        __syncthreads();

        // ======== act1 -> h1 splits into X1 (rows 48+j / 144+j) + head partials ========
#pragma unroll
        for (int i = 0; i < 6; i++) {
            int e = tid + NTHR * i, b = e & 31, j = e >> 5;
            float gi = GT[j * 34 + b]          + BI1[j];
            float gf = GT[(48 + j) * 34 + b]   + BI1[48 + j];
            float gg = GT[(96 + j) * 34 + b]   + BI1[96 + j];
            float go = GT[(144 + j) * 34 + b]  + BI1[144 + j];
            float c = fmaf(fsig(gf), c1[i], fsig(gi) * ftanh(gg));
            c1[i] = c;
            float h = fsig(go) * ftanh(c);
            X1u[(48 + j) * 40 + b]   = bfhi(h);
            X1u[(144 + j) * 40 + b]  = bflo(h);
            HP[j * 33 + b] = h * WLs[j];
        }
        __syncthreads();

        // ======== head: out(t) + next input into X0 rows 0/64 ========
        if (wid == 6) {
            int b = lane;
            float s = blv;
#pragma unroll 8
            for (int j = 0; j < 48; j++) s += HP[j * 33 + b];
            out[(size_t)(gb0 + b) * TTOT + t] = s;
            float nx = ((t + 1) < TOBS) ? xn : s;
            X0u[b]           = bfhi(nx);
            X0u[64 * 40 + b] = bflo(nx);
        }
        __syncthreads();
    }
}

extern "C" void kernel_launch(void* const* d_in, const int* in_sizes, int n_in,
                              void* d_out, int out_size)
{
    (void)in_sizes; (void)n_in; (void)out_size;
    const float* x    = (const float*)d_in[0];
    const float* wih0 = (const float*)d_in[1];
    const float* whh0 = (const float*)d_in[2];
    const float* bih0 = (const float*)d_in[3];
    const float* bhh0 = (const float*)d_in[4];
    const float* wih1 = (const float*)d_in[5];
    const float* whh1 = (const float*)d_in[6];
    const float* bih1 = (const float*)d_in[7];
    const float* bhh1 = (const float*)d_in[8];
    const float* wlin = (const float*)d_in[9];
    const float* blin = (const float*)d_in[10];
    float* out = (float*)d_out;

    cudaFuncSetAttribute(lstm576_hmma_kernel,
                         cudaFuncAttributeMaxDynamicSharedMemorySize, SMEM_BYTES);
    lstm576_hmma_kernel<<<NCTA, NTHR, SMEM_BYTES>>>(
        x, wih0, whh0, bih0, bhh0, wih1, whh1, bih1, bhh1, wlin, blin, out);
}